// round 15
// baseline (speedup 1.0000x reference)
#include <cuda_runtime.h>
#include <cuda_bf16.h>
#include <cuda_fp16.h>
#include <cstdint>

#define B_  32
#define T_  256
#define C_  2048
#define H_  16
#define D_  128
#define M_TOT (B_*T_)     // 8192
#define BH_  (B_*H_)      // 512

// ------------------------------------------------------------------
// Device globals
// ------------------------------------------------------------------
__device__ float g_cos[T_*64];
__device__ float g_sin[T_*64];
__device__ __half g_x16[(size_t)M_TOT*C_];
__device__ __half g_w16[(size_t)4*C_*C_];
__device__ __half g_y16[(size_t)M_TOT*C_];
__device__ __half g_qp[(size_t)BH_*T_*D_];    // pre-rope Q (fp16)
__device__ __half g_kp[(size_t)BH_*T_*D_];    // pre-rope K (fp16)
__device__ __half g_v16[(size_t)BH_*T_*D_];

// ------------------------------------------------------------------
// PTX helpers
// ------------------------------------------------------------------
__device__ __forceinline__ uint32_t smem_u32(const void* p) {
    uint32_t a;
    asm("{ .reg .u64 t; cvta.to.shared.u64 t, %1; cvt.u32.u64 %0, t; }" : "=r"(a) : "l"(p));
    return a;
}
__device__ __forceinline__ uint32_t h2u(__half2 h) {
    return *reinterpret_cast<uint32_t*>(&h);
}
__device__ __forceinline__ void cp16(uint32_t dst, const void* src) {
    asm volatile("cp.async.cg.shared.global [%0], [%1], 16;" :: "r"(dst), "l"(src));
}
__device__ __forceinline__ void cp_commit() {
    asm volatile("cp.async.commit_group;" ::: "memory");
}
__device__ __forceinline__ void sts128(uint32_t addr, uint32_t r0, uint32_t r1, uint32_t r2, uint32_t r3) {
    asm volatile("st.shared.v4.b32 [%0], {%1,%2,%3,%4};"
                 :: "r"(addr), "r"(r0), "r"(r1), "r"(r2), "r"(r3) : "memory");
}
__device__ __forceinline__ void ldmx4(uint32_t* r, uint32_t addr) {
    asm volatile("ldmatrix.sync.aligned.m8n8.x4.shared.b16 {%0,%1,%2,%3}, [%4];"
                 : "=r"(r[0]), "=r"(r[1]), "=r"(r[2]), "=r"(r[3]) : "r"(addr));
}
__device__ __forceinline__ void ldmx4t(uint32_t* r, uint32_t addr) {
    asm volatile("ldmatrix.sync.aligned.m8n8.x4.trans.shared.b16 {%0,%1,%2,%3}, [%4];"
                 : "=r"(r[0]), "=r"(r[1]), "=r"(r[2]), "=r"(r[3]) : "r"(addr));
}
__device__ __forceinline__ void mma16816h(float* d, const uint32_t* a, const uint32_t* b) {
    asm volatile(
        "mma.sync.aligned.m16n8k16.row.col.f32.f16.f16.f32 "
        "{%0,%1,%2,%3}, {%4,%5,%6,%7}, {%8,%9}, {%0,%1,%2,%3};"
        : "+f"(d[0]), "+f"(d[1]), "+f"(d[2]), "+f"(d[3])
        : "r"(a[0]), "r"(a[1]), "r"(a[2]), "r"(a[3]), "r"(b[0]), "r"(b[1]));
}
// Swizzle for [rows][32 x 16-bit] tiles (64B rows)
__device__ __forceinline__ uint32_t swz(int r, int c) {
    return (uint32_t)(r * 64 + ((c ^ ((r >> 1) & 3)) << 4));
}
// Swizzle for [rows][64 x 16-bit] tiles (128B rows)
__device__ __forceinline__ uint32_t swz128(int r, int c) {
    return (uint32_t)(r * 128 + ((c ^ (r & 7)) << 4));
}

#define SCALE 0.08838834764831845f

// ------------------------------------------------------------------
// Combined fp32 -> fp16 conversion for x and all 4 weights.
// grid.y 0..3: x quarter-segments; grid.y 4..7: weights 0..3.
// Each thread converts 4 float4s (MLP=4).
// ------------------------------------------------------------------
__global__ __launch_bounds__(256)
void split_all(const float4* __restrict__ x,
               const float4* __restrict__ w0, const float4* __restrict__ w1,
               const float4* __restrict__ w2, const float4* __restrict__ w3)
{
    const int seg = blockIdx.y;
    const float4* src;
    __half2* dp;
    int i0;
    if (seg < 4) {          // x: 4M float4s in 4 segments of 1M
        src = x + (size_t)seg * 1048576;
        dp  = (__half2*)g_x16 + (size_t)seg * 2097152;
        i0 = blockIdx.x * 1024 + threadIdx.x;     // blockIdx.x in [0,1024)
    } else {                // weights: 1M float4s each
        const int s = seg - 4;
        src = (s == 0) ? w0 : (s == 1) ? w1 : (s == 2) ? w2 : w3;
        dp  = (__half2*)(g_w16 + (size_t)s * C_ * C_);
        i0 = blockIdx.x * 1024 + threadIdx.x;
    }
    float4 v[4];
    #pragma unroll
    for (int k = 0; k < 4; k++) v[k] = src[i0 + k * 256];
    #pragma unroll
    for (int k = 0; k < 4; k++) {
        int i = i0 + k * 256;
        dp[2*i]   = __floats2half2_rn(v[k].x, v[k].y);
        dp[2*i+1] = __floats2half2_rn(v[k].z, v[k].w);
    }
}

// ------------------------------------------------------------------
// fp16 HMMA GEMM (128 thr, 4 warps 64x64, 3 stages, 2 CTA/SM)
// ------------------------------------------------------------------
#define G16_STAGE 32768             // A 16KB | B 16KB
#define G16_SMEM (1024 + 3*G16_STAGE)

__global__ __launch_bounds__(128, 2)
void gemm16(float* __restrict__ Out, int mode)
{
    extern __shared__ char dsm[];
    const int tid  = threadIdx.x;
    const int wid  = tid >> 5;
    const int lane = tid & 31;
    const int bn = blockIdx.x * 128;
    const int bm = blockIdx.y * 128;
    const int wz = blockIdx.z;

    const __half* A_g = (mode == 0) ? g_y16 : g_x16;
    const int widx = (mode == 0) ? 3 : wz;
    const __half* B_g = g_w16 + (size_t)widx * C_ * C_;

    const uint32_t base = (smem_u32(dsm) + 1023u) & ~1023u;

    auto load_stage = [&](int kt, int s) {
        const uint32_t sb = base + (uint32_t)s * G16_STAGE;
        const int kb = kt * 64;
        #pragma unroll
        for (int it = 0; it < 8; it++) {
            int idx = tid + it * 128;
            int r = idx >> 3, c = idx & 7;
            uint32_t off = swz128(r, c);
            cp16(sb + off,         A_g + (size_t)(bm + r) * C_ + kb + c * 8);
            cp16(sb + 16384 + off, B_g + (size_t)(bn + r) * C_ + kb + c * 8);
        }
        cp_commit();
    };

    const int wm = (wid >> 1) * 64;
    const int wn = (wid & 1) * 64;
    const int arow = wm + (lane & 15);
    const int acol_base = (lane >> 4);
    const int brow = wn + (lane & 7) + ((lane & 16) >> 1);
    const int bcol_base = ((lane >> 3) & 1);

    float acc[4][8][4];
    #pragma unroll
    for (int i = 0; i < 4; i++)
        #pragma unroll
        for (int j = 0; j < 8; j++)
            #pragma unroll
            for (int q = 0; q < 4; q++) acc[i][j][q] = 0.0f;

    const int NK = C_ / 64;

    load_stage(0, 0);
    load_stage(1, 1);

    for (int c = 0; c < NK; c++) {
        __syncthreads();
        if (c + 2 < NK) load_stage(c + 2, (c + 2) % 3);
        else            cp_commit();
        asm volatile("cp.async.wait_group 2;" ::: "memory");
        __syncthreads();

        const uint32_t sA = base + (uint32_t)(c % 3) * G16_STAGE;
        const uint32_t sB = sA + 16384;

        #pragma unroll
        for (int ks = 0; ks < 4; ks++) {
            uint32_t ah[4][4];
            #pragma unroll
            for (int mt = 0; mt < 4; mt++)
                ldmx4(ah[mt], sA + swz128(arow + mt * 16, ks * 2 + acol_base));
            uint32_t bh[8][2];
            #pragma unroll
            for (int ng = 0; ng < 4; ng++) {
                uint32_t q[4];
                ldmx4(q, sB + swz128(brow + ng * 16, ks * 2 + bcol_base));
                bh[2*ng][0] = q[0]; bh[2*ng][1] = q[1];
                bh[2*ng+1][0] = q[2]; bh[2*ng+1][1] = q[3];
            }
            #pragma unroll
            for (int mt = 0; mt < 4; mt++)
                #pragma unroll
                for (int nt = 0; nt < 8; nt++)
                    mma16816h(acc[mt][nt], ah[mt], bh[nt]);
        }
    }

    __half* qkv = (wz == 0) ? g_qp : (wz == 1) ? g_kp : g_v16;
    #pragma unroll
    for (int mt = 0; mt < 4; mt++) {
        const int row0 = bm + wm + mt * 16 + (lane >> 2);
        #pragma unroll
        for (int nt = 0; nt < 8; nt++) {
            const int col = bn + wn + nt * 8 + (lane & 3) * 2;
            #pragma unroll
            for (int half = 0; half < 2; half++) {
                const int row = row0 + half * 8;
                float y0 = acc[mt][nt][half * 2 + 0];
                float y1 = acc[mt][nt][half * 2 + 1];
                if (mode == 0) {
                    float2 v; v.x = y0; v.y = y1;
                    *(float2*)(Out + (size_t)row * C_ + col) = v;
                } else {
                    const int b = row >> 8, t = row & 255;
                    const int h = col >> 7, d0 = col & 127;
                    const size_t ix = (((size_t)b * H_ + h) * T_ + t) * D_ + d0;
                    *(__half2*)(qkv + ix) = __floats2half2_rn(y0, y1);
                }
            }
        }
    }
}

// ------------------------------------------------------------------
// RoPE tables
// ------------------------------------------------------------------
__global__ void rope_table_kernel()
{
    int idx = blockIdx.x * blockDim.x + threadIdx.x;
    if (idx >= T_ * 64) return;
    int j = idx & 63;
    int t = idx >> 6;
    double inv = exp(-(double)j * (9.210340371976184 / 64.0));
    double th = (double)t * inv;
    g_cos[idx] = (float)cos(th);
    g_sin[idx] = (float)sin(th);
}

// ------------------------------------------------------------------
// Unified fused attention: one CTA per bh handles BOTH q-blocks.
// V now has its OWN region; cp.async for V issued at kernel entry
// (overlaps the entire rope+QK+softmax phase).
// smem: Q[4][256][32] 64KB | K[4][256][32] 64KB | V[256][272B] 68KB = 196KB
// ------------------------------------------------------------------
#define AF_SQ  0
#define AF_SK  65536
#define AF_SV  131072
#define AF_SMEM (1024 + 131072 + 69632)    // 201,728 B

__global__ __launch_bounds__(256, 1)
void attn_all()
{
    extern __shared__ char dsm[];
    const int tid  = threadIdx.x;
    const int w    = tid >> 5;
    const int lane = tid & 31;
    const int bh   = blockIdx.x;

    const __half* Qg = g_qp + (size_t)bh * T_ * D_;
    const __half* Kg = g_kp + (size_t)bh * T_ * D_;
    const __half* Vg = g_v16 + (size_t)bh * T_ * D_;

    const uint32_t base = (smem_u32(dsm) + 1023u) & ~1023u;
    const uint32_t sQ = base + AF_SQ;
    const uint32_t sK = base + AF_SK;
    const uint32_t sV = base + AF_SV;

    // ---- V cp.async FIRST: overlaps all rope/QK/softmax work ----
    #pragma unroll
    for (int it = 0; it < 16; it++) {
        int idx = tid + it * 256;               // 0..4095
        int r = idx >> 4, dc = idx & 15;
        cp16(sV + (uint32_t)r * 272 + dc * 16, Vg + (size_t)r * D_ + dc * 8);
    }
    cp_commit();

    // ---- Q with RoPE (+1/sqrt(D)), all 256 rows ----
    #pragma unroll
    for (int it = 0; it < 8; it++) {
        int idx = tid + it * 256;               // 0..2047
        int r = idx >> 3, j8 = idx & 7;
        const __half* src = Qg + (size_t)r * D_ + j8 * 8;
        uint4 lo = *(const uint4*)(src);
        uint4 hi = *(const uint4*)(src + 64);
        const float4 c0 = *(const float4*)(g_cos + r * 64 + j8 * 8);
        const float4 c1 = *(const float4*)(g_cos + r * 64 + j8 * 8 + 4);
        const float4 s0 = *(const float4*)(g_sin + r * 64 + j8 * 8);
        const float4 s1 = *(const float4*)(g_sin + r * 64 + j8 * 8 + 4);
        const float cc[8] = {c0.x, c0.y, c0.z, c0.w, c1.x, c1.y, c1.z, c1.w};
        const float ss[8] = {s0.x, s0.y, s0.z, s0.w, s1.x, s1.y, s1.z, s1.w};
        uint32_t olo[4], ohi[4];
        #pragma unroll
        for (int i = 0; i < 4; i++) {
            float2 x0 = __half22float2(((const __half2*)&lo)[i]);
            float2 x1 = __half22float2(((const __half2*)&hi)[i]);
            float a0 = (x0.x * cc[2*i]   - x1.x * ss[2*i])   * SCALE;
            float a1 = (x0.y * cc[2*i+1] - x1.y * ss[2*i+1]) * SCALE;
            float b0 = (x1.x * cc[2*i]   + x0.x * ss[2*i])   * SCALE;
            float b1 = (x1.y * cc[2*i+1] + x0.y * ss[2*i+1]) * SCALE;
            olo[i] = h2u(__floats2half2_rn(a0, a1));
            ohi[i] = h2u(__floats2half2_rn(b0, b1));
        }
        sts128(sQ + (uint32_t)(j8 >> 2) * 16384 + swz(r, j8 & 3),       olo[0], olo[1], olo[2], olo[3]);
        sts128(sQ + (uint32_t)(2 + (j8 >> 2)) * 16384 + swz(r, j8 & 3), ohi[0], ohi[1], ohi[2], ohi[3]);
    }

    // ---- K with RoPE (no scale), all 256 rows ----
    #pragma unroll
    for (int it = 0; it < 8; it++) {
        int idx = tid + it * 256;
        int r = idx >> 3, j8 = idx & 7;
        const __half* src = Kg + (size_t)r * D_ + j8 * 8;
        uint4 lo = *(const uint4*)(src);
        uint4 hi = *(const uint4*)(src + 64);
        const float4 c0 = *(const float4*)(g_cos + r * 64 + j8 * 8);
        const float4 c1 = *(const float4*)(g_cos + r * 64 + j8 * 8 + 4);
        const float4 s0 = *(const float4*)(g_sin + r * 64 + j8 * 8);
        const float4 s1 = *(const float4*)(g_sin + r * 64 + j8 * 8 + 4);
        const float cc[8] = {c0.x, c0.y, c0.z, c0.w, c1.x, c1.y, c1.z, c1.w};
        const float ss[8] = {s0.x, s0.y, s0.z, s0.w, s1.x, s1.y, s1.z, s1.w};
        uint32_t olo[4], ohi[4];
        #pragma unroll
        for (int i = 0; i < 4; i++) {
            float2 x0 = __half22float2(((const __half2*)&lo)[i]);
            float2 x1 = __half22float2(((const __half2*)&hi)[i]);
            float a0 = x0.x * cc[2*i]   - x1.x * ss[2*i];
            float a1 = x0.y * cc[2*i+1] - x1.y * ss[2*i+1];
            float b0 = x1.x * cc[2*i]   + x0.x * ss[2*i];
            float b1 = x1.y * cc[2*i+1] + x0.y * ss[2*i+1];
            olo[i] = h2u(__floats2half2_rn(a0, a1));
            ohi[i] = h2u(__floats2half2_rn(b0, b1));
        }
        sts128(sK + (uint32_t)(j8 >> 2) * 16384 + swz(r, j8 & 3),       olo[0], olo[1], olo[2], olo[3]);
        sts128(sK + (uint32_t)(2 + (j8 >> 2)) * 16384 + swz(r, j8 & 3), ohi[0], ohi[1], ohi[2], ohi[3]);
    }
    __syncthreads();

    const int arowA = 128 + 16 * w + (lane & 15);
    const int arowB = 16 * w + (lane & 15);
    const int acol_base = (lane >> 4);
    const int brow_l = (lane & 7) + ((lane & 16) >> 1);
    const int bcol_base = ((lane >> 3) & 1);
    const float NEG = -1e30f;

    // ========== Phase A: rows 128..255 vs 256 keys ==========
    float accA[32][4];
    #pragma unroll
    for (int i = 0; i < 32; i++)
        #pragma unroll
        for (int q = 0; q < 4; q++) accA[i][q] = 0.0f;

    #pragma unroll
    for (int c4 = 0; c4 < 4; c4++) {
        #pragma unroll
        for (int ks = 0; ks < 2; ks++) {
            uint32_t qa[4];
            ldmx4(qa, sQ + (uint32_t)c4 * 16384 + swz(arowA, ks * 2 + acol_base));
            #pragma unroll
            for (int g = 0; g < 16; g++) {
                uint32_t bb[4];
                ldmx4(bb, sK + (uint32_t)c4 * 16384 + swz(g * 16 + brow_l, ks * 2 + bcol_base));
                mma16816h(accA[2*g],   qa, bb);
                mma16816h(accA[2*g+1], qa, bb + 2);
            }
        }
    }

    const int rowA_lo = 128 + 16 * w + (lane >> 2);
    const int rowA_hi = rowA_lo + 8;
    #pragma unroll
    for (int nt = 0; nt < 32; nt++) {
        const int col0 = nt * 8 + (lane & 3) * 2;
        if (col0     > rowA_lo) accA[nt][0] = NEG;
        if (col0 + 1 > rowA_lo) accA[nt][1] = NEG;
        if (col0     > rowA_hi) accA[nt][2] = NEG;
        if (col0 + 1 > rowA_hi) accA[nt][3] = NEG;
    }
    {
        float mlo = NEG, mhi = NEG;
        #pragma unroll
        for (int nt = 0; nt < 32; nt++) {
            mlo = fmaxf(mlo, fmaxf(accA[nt][0], accA[nt][1]));
            mhi = fmaxf(mhi, fmaxf(accA[nt][2], accA[nt][3]));
        }
        mlo = fmaxf(mlo, __shfl_xor_sync(0xffffffffu, mlo, 1));
        mlo = fmaxf(mlo, __shfl_xor_sync(0xffffffffu, mlo, 2));
        mhi = fmaxf(mhi, __shfl_xor_sync(0xffffffffu, mhi, 1));
        mhi = fmaxf(mhi, __shfl_xor_sync(0xffffffffu, mhi, 2));
        float slo = 0.f, shi = 0.f;
        #pragma unroll
        for (int nt = 0; nt < 32; nt++) {
            accA[nt][0] = __expf(accA[nt][0] - mlo);
            accA[nt][1] = __expf(accA[nt][1] - mlo);
            accA[nt][2] = __expf(accA[nt][2] - mhi);
            accA[nt][3] = __expf(accA[nt][3] - mhi);
            slo += accA[nt][0] + accA[nt][1];
            shi += accA[nt][2] + accA[nt][3];
        }
        slo += __shfl_xor_sync(0xffffffffu, slo, 1);
        slo += __shfl_xor_sync(0xffffffffu, slo, 2);
        shi += __shfl_xor_sync(0xffffffffu, shi, 1);
        shi += __shfl_xor_sync(0xffffffffu, shi, 2);
        const float ilo = 1.0f / slo;
        const float ihi = 1.0f / shi;
        #pragma unroll
        for (int nt = 0; nt < 32; nt++) {
            accA[nt][0] *= ilo; accA[nt][1] *= ilo;
            accA[nt][2] *= ihi; accA[nt][3] *= ihi;
        }
    }
    uint32_t pfA[16][4];
    #pragma unroll
    for (int j = 0; j < 16; j++) {
        pfA[j][0] = h2u(__floats2half2_rn(accA[2*j][0],   accA[2*j][1]));
        pfA[j][1] = h2u(__floats2half2_rn(accA[2*j][2],   accA[2*j][3]));
        pfA[j][2] = h2u(__floats2half2_rn(accA[2*j+1][0], accA[2*j+1][1]));
        pfA[j][3] = h2u(__floats2half2_rn(accA[2*j+1][2], accA[2*j+1][3]));
    }

    // ========== Phase B: rows 0..127 vs 128 keys ==========
    float accB[16][4];
    #pragma unroll
    for (int i = 0; i < 16; i++)
        #pragma unroll
        for (int q = 0; q < 4; q++) accB[i][q] = 0.0f;

    #pragma unroll
    for (int c4 = 0; c4 < 4; c4++) {
        #pragma unroll
        for (int ks = 0; ks < 2; ks++) {
            uint32_t qa[4];
            ldmx4(qa, sQ + (uint32_t)c4 * 16384 + swz(arowB, ks * 2 + acol_base));
            #pragma unroll
            for (int g = 0; g < 8; g++) {
                uint32_t bb[4];
                ldmx4(bb, sK + (uint32_t)c4 * 16384 + swz(g * 16 + brow_l, ks * 2 + bcol_base));
                mma16816h(accB[2*g],   qa, bb);
                mma16816h(accB[2*g+1], qa, bb + 2);
            }
        }
    }

    // softmax B
    const int rowB_lo = 16 * w + (lane >> 2);
    const int rowB_hi = rowB_lo + 8;
    #pragma unroll
    for (int nt = 0; nt < 16; nt++) {
        const int col0 = nt * 8 + (lane & 3) * 2;
        if (col0     > rowB_lo) accB[nt][0] = NEG;
        if (col0 + 1 > rowB_lo) accB[nt][1] = NEG;
        if (col0     > rowB_hi) accB[nt][2] = NEG;
        if (col0 + 1 > rowB_hi) accB[nt][3] = NEG;
    }
    uint32_t pfB[8][4];
    {
        float mlo = NEG, mhi = NEG;
        #pragma unroll
        for (int nt = 0; nt < 16; nt++) {
            mlo = fmaxf(mlo, fmaxf(accB[nt][0], accB[nt][1]));
            mhi = fmaxf(mhi, fmaxf(accB[nt][2], accB[nt][3]));
        }
        mlo = fmaxf(mlo, __shfl_xor_sync(0xffffffffu, mlo, 1));
        mlo = fmaxf(mlo, __shfl_xor_sync(0xffffffffu, mlo, 2));
        mhi = fmaxf(mhi, __shfl_xor_sync(0xffffffffu, mhi, 1));
        mhi = fmaxf(mhi, __shfl_xor_sync(0xffffffffu, mhi, 2));
        float slo = 0.f, shi = 0.f;
        #pragma unroll
        for (int nt = 0; nt < 16; nt++) {
            accB[nt][0] = __expf(accB[nt][0] - mlo);
            accB[nt][1] = __expf(accB[nt][1] - mlo);
            accB[nt][2] = __expf(accB[nt][2] - mhi);
            accB[nt][3] = __expf(accB[nt][3] - mhi);
            slo += accB[nt][0] + accB[nt][1];
            shi += accB[nt][2] + accB[nt][3];
        }
        slo += __shfl_xor_sync(0xffffffffu, slo, 1);
        slo += __shfl_xor_sync(0xffffffffu, slo, 2);
        shi += __shfl_xor_sync(0xffffffffu, shi, 1);
        shi += __shfl_xor_sync(0xffffffffu, shi, 2);
        const float ilo = 1.0f / slo;
        const float ihi = 1.0f / shi;
        #pragma unroll
        for (int j = 0; j < 8; j++) {
            pfB[j][0] = h2u(__floats2half2_rn(accB[2*j][0] * ilo,   accB[2*j][1] * ilo));
            pfB[j][1] = h2u(__floats2half2_rn(accB[2*j][2] * ihi,   accB[2*j][3] * ihi));
            pfB[j][2] = h2u(__floats2half2_rn(accB[2*j+1][0] * ilo, accB[2*j+1][1] * ilo));
            pfB[j][3] = h2u(__floats2half2_rn(accB[2*j+1][2] * ihi, accB[2*j+1][3] * ihi));
        }
    }

    asm volatile("cp.async.wait_group 0;" ::: "memory");
    __syncthreads();

    const int kl_part = ((lane >> 3) & 1) * 8 + (lane & 7);
    const int nblk = lane >> 4;
    const int b = bh >> 4, h = bh & 15;

    // ---- PV phase A (256 keys) + epilogue A ----
    {
        float oacc[16][4];
        #pragma unroll
        for (int i = 0; i < 16; i++)
            #pragma unroll
            for (int q = 0; q < 4; q++) oacc[i][q] = 0.0f;
        #pragma unroll
        for (int j = 0; j < 16; j++) {
            #pragma unroll
            for (int dp = 0; dp < 8; dp++) {
                uint32_t bb[4];
                ldmx4t(bb, sV + (uint32_t)(j * 16 + kl_part) * 272 + (uint32_t)(dp * 2 + nblk) * 16);
                mma16816h(oacc[2*dp],   pfA[j], bb);
                mma16816h(oacc[2*dp+1], pfA[j], bb + 2);
            }
        }
        #pragma unroll
        for (int nt = 0; nt < 16; nt++) {
            const int d = nt * 8 + (lane & 3) * 2;
            const size_t ix_lo = ((size_t)b * T_ + rowA_lo) * C_ + h * D_ + d;
            const size_t ix_hi = ((size_t)b * T_ + rowA_hi) * C_ + h * D_ + d;
            *(__half2*)(g_y16 + ix_lo) = __floats2half2_rn(oacc[nt][0], oacc[nt][1]);
            *(__half2*)(g_y16 + ix_hi) = __floats2half2_rn(oacc[nt][2], oacc[nt][3]);
        }
    }

    // ---- PV phase B (128 keys) + epilogue B ----
    {
        float oacc[16][4];
        #pragma unroll
        for (int i = 0; i < 16; i++)
            #pragma unroll
            for (int q = 0; q < 4; q++) oacc[i][q] = 0.0f;
        #pragma unroll
        for (int j = 0; j < 8; j++) {
            #pragma unroll
            for (int dp = 0; dp < 8; dp++) {
                uint32_t bb[4];
                ldmx4t(bb, sV + (uint32_t)(j * 16 + kl_part) * 272 + (uint32_t)(dp * 2 + nblk) * 16);
                mma16816h(oacc[2*dp],   pfB[j], bb);
                mma16816h(oacc[2*dp+1], pfB[j], bb + 2);
            }
        }
        #pragma unroll
        for (int nt = 0; nt < 16; nt++) {
            const int d = nt * 8 + (lane & 3) * 2;
            const size_t ix_lo = ((size_t)b * T_ + rowB_lo) * C_ + h * D_ + d;
            const size_t ix_hi = ((size_t)b * T_ + rowB_hi) * C_ + h * D_ + d;
            *(__half2*)(g_y16 + ix_lo) = __floats2half2_rn(oacc[nt][0], oacc[nt][1]);
            *(__half2*)(g_y16 + ix_hi) = __floats2half2_rn(oacc[nt][2], oacc[nt][3]);
        }
    }
}

// ------------------------------------------------------------------
extern "C" void kernel_launch(void* const* d_in, const int* in_sizes, int n_in,
                              void* d_out, int out_size)
{
    const float* x  = (const float*)d_in[0];
    const float* wq = (const float*)d_in[1];
    const float* wk = (const float*)d_in[2];
    const float* wv = (const float*)d_in[3];
    const float* wo = (const float*)d_in[4];
    float* out = (float*)d_out;

    cudaFuncSetAttribute(gemm16, cudaFuncAttributeMaxDynamicSharedMemorySize, G16_SMEM);
    cudaFuncSetAttribute(attn_all, cudaFuncAttributeMaxDynamicSharedMemorySize, AF_SMEM);

    // #1: all conversions in one launch (x: 4 segs of 1024 blocks; w: 4 x 1024)
    split_all<<<dim3(1024, 8), 256>>>((const float4*)x, (const float4*)wq,
                                      (const float4*)wk, (const float4*)wv,
                                      (const float4*)wo);
    // #2: rope tables
    rope_table_kernel<<<(T_*64 + 255)/256, 256>>>();

    // #3: QKV projections
    gemm16<<<dim3(C_/128, M_TOT/128, 3), 128, G16_SMEM>>>(nullptr, 1);

    // #4: unified fused attention (ncu capture target)
    attn_all<<<BH_, 256, AF_SMEM>>>();

    // #5: output projection
    gemm16<<<dim3(C_/128, M_TOT/128, 1), 128, G16_SMEM>>>(out, 0);
}

// round 16
// speedup vs baseline: 1.0208x; 1.0208x over previous
#include <cuda_runtime.h>
#include <cuda_bf16.h>
#include <cuda_fp16.h>
#include <cstdint>

#define B_  32
#define T_  256
#define C_  2048
#define H_  16
#define D_  128
#define M_TOT (B_*T_)     // 8192
#define BH_  (B_*H_)      // 512

// ------------------------------------------------------------------
// Device globals
// ------------------------------------------------------------------
__device__ float g_cos[T_*64];
__device__ float g_sin[T_*64];
__device__ __half g_x16[(size_t)M_TOT*C_];
__device__ __half g_w16[(size_t)4*C_*C_];
__device__ __half g_y16[(size_t)M_TOT*C_];
__device__ __half g_qp[(size_t)BH_*T_*D_];    // pre-rope Q (fp16)
__device__ __half g_kp[(size_t)BH_*T_*D_];    // pre-rope K (fp16)
__device__ __half g_v16[(size_t)BH_*T_*D_];

// ------------------------------------------------------------------
// PTX helpers
// ------------------------------------------------------------------
__device__ __forceinline__ uint32_t smem_u32(const void* p) {
    uint32_t a;
    asm("{ .reg .u64 t; cvta.to.shared.u64 t, %1; cvt.u32.u64 %0, t; }" : "=r"(a) : "l"(p));
    return a;
}
__device__ __forceinline__ uint32_t h2u(__half2 h) {
    return *reinterpret_cast<uint32_t*>(&h);
}
__device__ __forceinline__ void cp16(uint32_t dst, const void* src) {
    asm volatile("cp.async.cg.shared.global [%0], [%1], 16;" :: "r"(dst), "l"(src));
}
__device__ __forceinline__ void cp_commit() {
    asm volatile("cp.async.commit_group;" ::: "memory");
}
__device__ __forceinline__ void sts128(uint32_t addr, uint32_t r0, uint32_t r1, uint32_t r2, uint32_t r3) {
    asm volatile("st.shared.v4.b32 [%0], {%1,%2,%3,%4};"
                 :: "r"(addr), "r"(r0), "r"(r1), "r"(r2), "r"(r3) : "memory");
}
__device__ __forceinline__ void ldmx4(uint32_t* r, uint32_t addr) {
    asm volatile("ldmatrix.sync.aligned.m8n8.x4.shared.b16 {%0,%1,%2,%3}, [%4];"
                 : "=r"(r[0]), "=r"(r[1]), "=r"(r[2]), "=r"(r[3]) : "r"(addr));
}
__device__ __forceinline__ void ldmx4t(uint32_t* r, uint32_t addr) {
    asm volatile("ldmatrix.sync.aligned.m8n8.x4.trans.shared.b16 {%0,%1,%2,%3}, [%4];"
                 : "=r"(r[0]), "=r"(r[1]), "=r"(r[2]), "=r"(r[3]) : "r"(addr));
}
__device__ __forceinline__ void mma16816h(float* d, const uint32_t* a, const uint32_t* b) {
    asm volatile(
        "mma.sync.aligned.m16n8k16.row.col.f32.f16.f16.f32 "
        "{%0,%1,%2,%3}, {%4,%5,%6,%7}, {%8,%9}, {%0,%1,%2,%3};"
        : "+f"(d[0]), "+f"(d[1]), "+f"(d[2]), "+f"(d[3])
        : "r"(a[0]), "r"(a[1]), "r"(a[2]), "r"(a[3]), "r"(b[0]), "r"(b[1]));
}
// Swizzle for [rows][32 x 16-bit] tiles (64B rows)
__device__ __forceinline__ uint32_t swz(int r, int c) {
    return (uint32_t)(r * 64 + ((c ^ ((r >> 1) & 3)) << 4));
}
// Swizzle for [rows][64 x 16-bit] tiles (128B rows)
__device__ __forceinline__ uint32_t swz128(int r, int c) {
    return (uint32_t)(r * 128 + ((c ^ (r & 7)) << 4));
}

#define SCALE 0.08838834764831845f

// ------------------------------------------------------------------
// Combined fp32 -> fp16 conversion for x and all 4 weights.
// grid.y 0..3: x quarter-segments; grid.y 4..7: weights 0..3.
// ------------------------------------------------------------------
__global__ __launch_bounds__(256)
void split_all(const float4* __restrict__ x,
               const float4* __restrict__ w0, const float4* __restrict__ w1,
               const float4* __restrict__ w2, const float4* __restrict__ w3)
{
    const int seg = blockIdx.y;
    const float4* src;
    __half2* dp;
    if (seg < 4) {
        src = x + (size_t)seg * 1048576;
        dp  = (__half2*)g_x16 + (size_t)seg * 2097152;
    } else {
        const int s = seg - 4;
        src = (s == 0) ? w0 : (s == 1) ? w1 : (s == 2) ? w2 : w3;
        dp  = (__half2*)(g_w16 + (size_t)s * C_ * C_);
    }
    int i0 = blockIdx.x * 1024 + threadIdx.x;
    float4 v[4];
    #pragma unroll
    for (int k = 0; k < 4; k++) v[k] = src[i0 + k * 256];
    #pragma unroll
    for (int k = 0; k < 4; k++) {
        int i = i0 + k * 256;
        dp[2*i]   = __floats2half2_rn(v[k].x, v[k].y);
        dp[2*i+1] = __floats2half2_rn(v[k].z, v[k].w);
    }
}

// ------------------------------------------------------------------
// fp16 HMMA GEMM (128 thr, 4 warps 64x64, 3 stages, 2 CTA/SM)
// ------------------------------------------------------------------
#define G16_STAGE 32768             // A 16KB | B 16KB
#define G16_SMEM (1024 + 3*G16_STAGE)

__global__ __launch_bounds__(128, 2)
void gemm16(float* __restrict__ Out, int mode)
{
    extern __shared__ char dsm[];
    const int tid  = threadIdx.x;
    const int wid  = tid >> 5;
    const int lane = tid & 31;
    const int bn = blockIdx.x * 128;
    const int bm = blockIdx.y * 128;
    const int wz = blockIdx.z;

    const __half* A_g = (mode == 0) ? g_y16 : g_x16;
    const int widx = (mode == 0) ? 3 : wz;
    const __half* B_g = g_w16 + (size_t)widx * C_ * C_;

    const uint32_t base = (smem_u32(dsm) + 1023u) & ~1023u;

    auto load_stage = [&](int kt, int s) {
        const uint32_t sb = base + (uint32_t)s * G16_STAGE;
        const int kb = kt * 64;
        #pragma unroll
        for (int it = 0; it < 8; it++) {
            int idx = tid + it * 128;
            int r = idx >> 3, c = idx & 7;
            uint32_t off = swz128(r, c);
            cp16(sb + off,         A_g + (size_t)(bm + r) * C_ + kb + c * 8);
            cp16(sb + 16384 + off, B_g + (size_t)(bn + r) * C_ + kb + c * 8);
        }
        cp_commit();
    };

    const int wm = (wid >> 1) * 64;
    const int wn = (wid & 1) * 64;
    const int arow = wm + (lane & 15);
    const int acol_base = (lane >> 4);
    const int brow = wn + (lane & 7) + ((lane & 16) >> 1);
    const int bcol_base = ((lane >> 3) & 1);

    float acc[4][8][4];
    #pragma unroll
    for (int i = 0; i < 4; i++)
        #pragma unroll
        for (int j = 0; j < 8; j++)
            #pragma unroll
            for (int q = 0; q < 4; q++) acc[i][j][q] = 0.0f;

    const int NK = C_ / 64;

    load_stage(0, 0);
    load_stage(1, 1);

    for (int c = 0; c < NK; c++) {
        __syncthreads();
        if (c + 2 < NK) load_stage(c + 2, (c + 2) % 3);
        else            cp_commit();
        asm volatile("cp.async.wait_group 2;" ::: "memory");
        __syncthreads();

        const uint32_t sA = base + (uint32_t)(c % 3) * G16_STAGE;
        const uint32_t sB = sA + 16384;

        #pragma unroll
        for (int ks = 0; ks < 4; ks++) {
            uint32_t ah[4][4];
            #pragma unroll
            for (int mt = 0; mt < 4; mt++)
                ldmx4(ah[mt], sA + swz128(arow + mt * 16, ks * 2 + acol_base));
            uint32_t bh[8][2];
            #pragma unroll
            for (int ng = 0; ng < 4; ng++) {
                uint32_t q[4];
                ldmx4(q, sB + swz128(brow + ng * 16, ks * 2 + bcol_base));
                bh[2*ng][0] = q[0]; bh[2*ng][1] = q[1];
                bh[2*ng+1][0] = q[2]; bh[2*ng+1][1] = q[3];
            }
            #pragma unroll
            for (int mt = 0; mt < 4; mt++)
                #pragma unroll
                for (int nt = 0; nt < 8; nt++)
                    mma16816h(acc[mt][nt], ah[mt], bh[nt]);
        }
    }

    __half* qkv = (wz == 0) ? g_qp : (wz == 1) ? g_kp : g_v16;
    #pragma unroll
    for (int mt = 0; mt < 4; mt++) {
        const int row0 = bm + wm + mt * 16 + (lane >> 2);
        #pragma unroll
        for (int nt = 0; nt < 8; nt++) {
            const int col = bn + wn + nt * 8 + (lane & 3) * 2;
            #pragma unroll
            for (int half = 0; half < 2; half++) {
                const int row = row0 + half * 8;
                float y0 = acc[mt][nt][half * 2 + 0];
                float y1 = acc[mt][nt][half * 2 + 1];
                if (mode == 0) {
                    float2 v; v.x = y0; v.y = y1;
                    *(float2*)(Out + (size_t)row * C_ + col) = v;
                } else {
                    const int b = row >> 8, t = row & 255;
                    const int h = col >> 7, d0 = col & 127;
                    const size_t ix = (((size_t)b * H_ + h) * T_ + t) * D_ + d0;
                    *(__half2*)(qkv + ix) = __floats2half2_rn(y0, y1);
                }
            }
        }
    }
}

// ------------------------------------------------------------------
// RoPE tables
// ------------------------------------------------------------------
__global__ void rope_table_kernel()
{
    int idx = blockIdx.x * blockDim.x + threadIdx.x;
    if (idx >= T_ * 64) return;
    int j = idx & 63;
    int t = idx >> 6;
    double inv = exp(-(double)j * (9.210340371976184 / 64.0));
    double th = (double)t * inv;
    g_cos[idx] = (float)cos(th);
    g_sin[idx] = (float)sin(th);
}

// ------------------------------------------------------------------
// Fused flash attention with in-kernel RoPE (R13 two-template form).
// KT = number of 128-key tiles. One CTA per bh per q-block.
// smem: Q[4][128][32] 32KB | K[4][KT*128][32] | V[KT*128][272B]
// KT=1 total 98KB -> 2 CTAs/SM; KT=2 total 164KB -> 1 CTA/SM.
// V cp.async issued at kernel entry (overlaps rope+QK+softmax).
// ------------------------------------------------------------------
#define AF_SQ 0
#define AF_SK 32768
#define AF_SMEM(KT) (1024 + 32768 + (KT)*32768 + (KT)*34816)

template<int KT>
__global__ __launch_bounds__(256, 1)
void attn_fused()
{
    extern __shared__ char dsm[];
    const int tid  = threadIdx.x;
    const int w    = tid >> 5;
    const int lane = tid & 31;
    const int bh   = blockIdx.x;
    const int qt   = KT - 1;

    const __half* Qg = g_qp + ((size_t)bh * T_ + qt * 128) * D_;
    const __half* Kg = g_kp + (size_t)bh * T_ * D_;
    const __half* Vg = g_v16 + (size_t)bh * T_ * D_;

    const uint32_t base = (smem_u32(dsm) + 1023u) & ~1023u;
    const uint32_t sQ = base + AF_SQ;
    const uint32_t sK = base + AF_SK;
    const uint32_t sV = base + AF_SK + (uint32_t)KT * 32768;

    // ---- V cp.async first: overlaps rope + QK + softmax ----
    #pragma unroll
    for (int it = 0; it < KT * 8; it++) {
        int idx = tid + it * 256;
        int r = idx >> 4, dc = idx & 15;
        cp16(sV + (uint32_t)r * 272 + dc * 16, Vg + (size_t)r * D_ + dc * 8);
    }
    cp_commit();

    // ---- Q with RoPE (+1/sqrt(D)) ----
    #pragma unroll
    for (int it = 0; it < 4; it++) {
        int idx = tid + it * 256;               // 0..1023
        int r = idx >> 3, j8 = idx & 7;
        const __half* src = Qg + (size_t)r * D_ + j8 * 8;
        uint4 lo = *(const uint4*)(src);
        uint4 hi = *(const uint4*)(src + 64);
        const int tg = qt * 128 + r;
        const float4 c0 = *(const float4*)(g_cos + tg * 64 + j8 * 8);
        const float4 c1 = *(const float4*)(g_cos + tg * 64 + j8 * 8 + 4);
        const float4 s0 = *(const float4*)(g_sin + tg * 64 + j8 * 8);
        const float4 s1 = *(const float4*)(g_sin + tg * 64 + j8 * 8 + 4);
        const float cc[8] = {c0.x, c0.y, c0.z, c0.w, c1.x, c1.y, c1.z, c1.w};
        const float ss[8] = {s0.x, s0.y, s0.z, s0.w, s1.x, s1.y, s1.z, s1.w};
        uint32_t olo[4], ohi[4];
        #pragma unroll
        for (int i = 0; i < 4; i++) {
            float2 x0 = __half22float2(((const __half2*)&lo)[i]);
            float2 x1 = __half22float2(((const __half2*)&hi)[i]);
            float a0 = (x0.x * cc[2*i]   - x1.x * ss[2*i])   * SCALE;
            float a1 = (x0.y * cc[2*i+1] - x1.y * ss[2*i+1]) * SCALE;
            float b0 = (x1.x * cc[2*i]   + x0.x * ss[2*i])   * SCALE;
            float b1 = (x1.y * cc[2*i+1] + x0.y * ss[2*i+1]) * SCALE;
            olo[i] = h2u(__floats2half2_rn(a0, a1));
            ohi[i] = h2u(__floats2half2_rn(b0, b1));
        }
        sts128(sQ + (uint32_t)(j8 >> 2) * 8192 + swz(r, j8 & 3),       olo[0], olo[1], olo[2], olo[3]);
        sts128(sQ + (uint32_t)(2 + (j8 >> 2)) * 8192 + swz(r, j8 & 3), ohi[0], ohi[1], ohi[2], ohi[3]);
    }

    // ---- K with RoPE (no scale) ----
    #pragma unroll
    for (int it = 0; it < KT * 4; it++) {
        int idx = tid + it * 256;
        int r = idx >> 3, j8 = idx & 7;
        const __half* src = Kg + (size_t)r * D_ + j8 * 8;
        uint4 lo = *(const uint4*)(src);
        uint4 hi = *(const uint4*)(src + 64);
        const float4 c0 = *(const float4*)(g_cos + r * 64 + j8 * 8);
        const float4 c1 = *(const float4*)(g_cos + r * 64 + j8 * 8 + 4);
        const float4 s0 = *(const float4*)(g_sin + r * 64 + j8 * 8);
        const float4 s1 = *(const float4*)(g_sin + r * 64 + j8 * 8 + 4);
        const float cc[8] = {c0.x, c0.y, c0.z, c0.w, c1.x, c1.y, c1.z, c1.w};
        const float ss[8] = {s0.x, s0.y, s0.z, s0.w, s1.x, s1.y, s1.z, s1.w};
        uint32_t olo[4], ohi[4];
        #pragma unroll
        for (int i = 0; i < 4; i++) {
            float2 x0 = __half22float2(((const __half2*)&lo)[i]);
            float2 x1 = __half22float2(((const __half2*)&hi)[i]);
            float a0 = x0.x * cc[2*i]   - x1.x * ss[2*i];
            float a1 = x0.y * cc[2*i+1] - x1.y * ss[2*i+1];
            float b0 = x1.x * cc[2*i]   + x0.x * ss[2*i];
            float b1 = x1.y * cc[2*i+1] + x0.y * ss[2*i+1];
            olo[i] = h2u(__floats2half2_rn(a0, a1));
            ohi[i] = h2u(__floats2half2_rn(b0, b1));
        }
        sts128(sK + (uint32_t)(j8 >> 2) * (KT * 8192) + swz(r, j8 & 3),       olo[0], olo[1], olo[2], olo[3]);
        sts128(sK + (uint32_t)(2 + (j8 >> 2)) * (KT * 8192) + swz(r, j8 & 3), ohi[0], ohi[1], ohi[2], ohi[3]);
    }
    __syncthreads();

    // ---- S = Q K^T ----
    const int NT = KT * 16;
    const int arow = 16 * w + (lane & 15);
    const int acol_base = (lane >> 4);
    const int brow_l = (lane & 7) + ((lane & 16) >> 1);
    const int bcol_base = ((lane >> 3) & 1);

    float acc[NT][4];
    #pragma unroll
    for (int i = 0; i < NT; i++)
        #pragma unroll
        for (int q = 0; q < 4; q++) acc[i][q] = 0.0f;

    #pragma unroll
    for (int c4 = 0; c4 < 4; c4++) {
        #pragma unroll
        for (int ks = 0; ks < 2; ks++) {
            uint32_t qa[4];
            ldmx4(qa, sQ + (uint32_t)c4 * 8192 + swz(arow, ks * 2 + acol_base));
            #pragma unroll
            for (int g = 0; g < KT * 8; g++) {
                uint32_t bb[4];
                ldmx4(bb, sK + (uint32_t)c4 * (KT * 8192) + swz(g * 16 + brow_l, ks * 2 + bcol_base));
                mma16816h(acc[2*g],   qa, bb);
                mma16816h(acc[2*g+1], qa, bb + 2);
            }
        }
    }

    // ---- causal mask + softmax ----
    const int row_lo = qt * 128 + 16 * w + (lane >> 2);
    const int row_hi = row_lo + 8;
    const float NEG = -1e30f;
    #pragma unroll
    for (int nt = 0; nt < NT; nt++) {
        const int col0 = nt * 8 + (lane & 3) * 2;
        if (col0     > row_lo) acc[nt][0] = NEG;
        if (col0 + 1 > row_lo) acc[nt][1] = NEG;
        if (col0     > row_hi) acc[nt][2] = NEG;
        if (col0 + 1 > row_hi) acc[nt][3] = NEG;
    }
    float mlo = NEG, mhi = NEG;
    #pragma unroll
    for (int nt = 0; nt < NT; nt++) {
        mlo = fmaxf(mlo, fmaxf(acc[nt][0], acc[nt][1]));
        mhi = fmaxf(mhi, fmaxf(acc[nt][2], acc[nt][3]));
    }
    mlo = fmaxf(mlo, __shfl_xor_sync(0xffffffffu, mlo, 1));
    mlo = fmaxf(mlo, __shfl_xor_sync(0xffffffffu, mlo, 2));
    mhi = fmaxf(mhi, __shfl_xor_sync(0xffffffffu, mhi, 1));
    mhi = fmaxf(mhi, __shfl_xor_sync(0xffffffffu, mhi, 2));
    float slo = 0.f, shi = 0.f;
    #pragma unroll
    for (int nt = 0; nt < NT; nt++) {
        acc[nt][0] = __expf(acc[nt][0] - mlo);
        acc[nt][1] = __expf(acc[nt][1] - mlo);
        acc[nt][2] = __expf(acc[nt][2] - mhi);
        acc[nt][3] = __expf(acc[nt][3] - mhi);
        slo += acc[nt][0] + acc[nt][1];
        shi += acc[nt][2] + acc[nt][3];
    }
    slo += __shfl_xor_sync(0xffffffffu, slo, 1);
    slo += __shfl_xor_sync(0xffffffffu, slo, 2);
    shi += __shfl_xor_sync(0xffffffffu, shi, 1);
    shi += __shfl_xor_sync(0xffffffffu, shi, 2);
    const float ilo = 1.0f / slo;
    const float ihi = 1.0f / shi;

    uint32_t pf[KT * 8][4];
    #pragma unroll
    for (int j = 0; j < KT * 8; j++) {
        pf[j][0] = h2u(__floats2half2_rn(acc[2*j][0] * ilo, acc[2*j][1] * ilo));
        pf[j][1] = h2u(__floats2half2_rn(acc[2*j][2] * ihi, acc[2*j][3] * ihi));
        pf[j][2] = h2u(__floats2half2_rn(acc[2*j+1][0] * ilo, acc[2*j+1][1] * ilo));
        pf[j][3] = h2u(__floats2half2_rn(acc[2*j+1][2] * ihi, acc[2*j+1][3] * ihi));
    }

    asm volatile("cp.async.wait_group 0;" ::: "memory");
    __syncthreads();

    // ---- O = P V ----
    const int kl_part = ((lane >> 3) & 1) * 8 + (lane & 7);
    const int nblk = lane >> 4;

    float oacc[16][4];
    #pragma unroll
    for (int i = 0; i < 16; i++)
        #pragma unroll
        for (int q = 0; q < 4; q++) oacc[i][q] = 0.0f;

    #pragma unroll
    for (int j = 0; j < KT * 8; j++) {
        #pragma unroll
        for (int dp = 0; dp < 8; dp++) {
            uint32_t bb[4];
            ldmx4t(bb, sV + (uint32_t)(j * 16 + kl_part) * 272 + (uint32_t)(dp * 2 + nblk) * 16);
            mma16816h(oacc[2*dp],   pf[j], bb);
            mma16816h(oacc[2*dp+1], pf[j], bb + 2);
        }
    }

    // ---- epilogue: y fp16 [B, T, C] ----
    const int b = bh >> 4, h = bh & 15;
    #pragma unroll
    for (int nt = 0; nt < 16; nt++) {
        const int d = nt * 8 + (lane & 3) * 2;
        const size_t ix_lo = ((size_t)b * T_ + row_lo) * C_ + h * D_ + d;
        const size_t ix_hi = ((size_t)b * T_ + row_hi) * C_ + h * D_ + d;
        *(__half2*)(g_y16 + ix_lo) = __floats2half2_rn(oacc[nt][0], oacc[nt][1]);
        *(__half2*)(g_y16 + ix_hi) = __floats2half2_rn(oacc[nt][2], oacc[nt][3]);
    }
}

// ------------------------------------------------------------------
extern "C" void kernel_launch(void* const* d_in, const int* in_sizes, int n_in,
                              void* d_out, int out_size)
{
    const float* x  = (const float*)d_in[0];
    const float* wq = (const float*)d_in[1];
    const float* wk = (const float*)d_in[2];
    const float* wv = (const float*)d_in[3];
    const float* wo = (const float*)d_in[4];
    float* out = (float*)d_out;

    cudaFuncSetAttribute(gemm16, cudaFuncAttributeMaxDynamicSharedMemorySize, G16_SMEM);
    cudaFuncSetAttribute(attn_fused<1>, cudaFuncAttributeMaxDynamicSharedMemorySize, AF_SMEM(1));
    cudaFuncSetAttribute(attn_fused<2>, cudaFuncAttributeMaxDynamicSharedMemorySize, AF_SMEM(2));

    // #1: all conversions in one launch
    split_all<<<dim3(1024, 8), 256>>>((const float4*)x, (const float4*)wq,
                                      (const float4*)wk, (const float4*)wv,
                                      (const float4*)wo);
    // #2: rope tables
    rope_table_kernel<<<(T_*64 + 255)/256, 256>>>();

    // #3: QKV projections
    gemm16<<<dim3(C_/128, M_TOT/128, 3), 128, G16_SMEM>>>(nullptr, 1);

    // #4/#5: fused attention (rope in-kernel); light kernel gets 2 CTA/SM
    attn_fused<2><<<BH_, 256, AF_SMEM(2)>>>();
    attn_fused<1><<<BH_, 256, AF_SMEM(1)>>>();

    // #6: output projection
    gemm16<<<dim3(C_/128, M_TOT/128, 1), 128, G16_SMEM>>>(out, 0);
}